// round 16
// baseline (speedup 1.0000x reference)
#include <cuda_runtime.h>
#include <cuda_fp16.h>
#include <cstdint>
#include <math.h>

#define BATCH 4
#define SEQ   2048
#define DIM   1024
#define HEADS 16
#define DHEAD 64
#define INNER 1024
#define QKV3  3072
#define SCALE 0.125f
#define NEGV  (-1e9f)
#define MTOT  (BATCH * SEQ)   // 8192

// ---------------------------------------------------------------------------
// Device scratch (allocation-free)
// ---------------------------------------------------------------------------
__device__ __half  g_qkvh[(size_t)MTOT * QKV3];
__device__ __half  g_xh[(size_t)MTOT * DIM];
__device__ __half  g_wqkv_h[(size_t)QKV3 * DIM];   // [N][K]
__device__ __half  g_wout_h[(size_t)DIM * INNER];  // [N][K]
__device__ __half  g_attnh[(size_t)MTOT * INNER];

// ---------------------------------------------------------------------------
__device__ __forceinline__ uint32_t smem_to_u32(const void* p) {
    uint32_t a;
    asm("{ .reg .u64 t; cvta.to.shared.u64 t, %1; cvt.u32.u64 %0, t; }" : "=r"(a) : "l"(p));
    return a;
}
__device__ __forceinline__ void ldsm4(uint32_t (&r)[4], uint32_t addr) {
    asm volatile("ldmatrix.sync.aligned.m8n8.x4.shared.b16 {%0,%1,%2,%3}, [%4];"
        : "=r"(r[0]), "=r"(r[1]), "=r"(r[2]), "=r"(r[3]) : "r"(addr));
}
__device__ __forceinline__ void ldsm4t(uint32_t (&r)[4], uint32_t addr) {
    asm volatile("ldmatrix.sync.aligned.m8n8.x4.trans.shared.b16 {%0,%1,%2,%3}, [%4];"
        : "=r"(r[0]), "=r"(r[1]), "=r"(r[2]), "=r"(r[3]) : "r"(addr));
}
__device__ __forceinline__ void mma16816(float (&d)[4], const uint32_t (&a)[4],
                                         uint32_t b0, uint32_t b1) {
    asm volatile("mma.sync.aligned.m16n8k16.row.col.f32.f16.f16.f32 "
        "{%0,%1,%2,%3}, {%4,%5,%6,%7}, {%8,%9}, {%0,%1,%2,%3};"
        : "+f"(d[0]), "+f"(d[1]), "+f"(d[2]), "+f"(d[3])
        : "r"(a[0]), "r"(a[1]), "r"(a[2]), "r"(a[3]), "r"(b0), "r"(b1));
}
__device__ __forceinline__ void cpasync16(uint32_t dst, const void* src) {
    asm volatile("cp.async.cg.shared.global [%0], [%1], 16;" :: "r"(dst), "l"(src));
}
#define CP_COMMIT  asm volatile("cp.async.commit_group;" ::: "memory")
#define CP_WAIT1   asm volatile("cp.async.wait_group 1;" ::: "memory")
#define CP_WAIT0   asm volatile("cp.async.wait_group 0;" ::: "memory")

__device__ __forceinline__ uint32_t packh(__half a, __half b) {
    return (uint32_t)__half_as_ushort(a) | ((uint32_t)__half_as_ushort(b) << 16);
}
__device__ __forceinline__ uint32_t packh2f(float a, float b) {
    return packh(__float2half_rn(a), __float2half_rn(b));
}

// ---------------------------------------------------------------------------
// Conversion kernels
// ---------------------------------------------------------------------------
__global__ __launch_bounds__(256)
void round_rows(const float* __restrict__ in, __half* __restrict__ hi, int n4)
{
    int i = blockIdx.x * 256 + threadIdx.x;
    if (i >= n4) return;
    float4 v = ((const float4*)in)[i];
    uint2 hv;
    hv.x = packh2f(v.x, v.y);
    hv.y = packh2f(v.z, v.w);
    ((uint2*)hi)[i] = hv;
}

// in[K][N] -> out[N][K], single-fp16 round
__global__ __launch_bounds__(256)
void round_T(const float* __restrict__ in, __half* __restrict__ hi, int K, int N)
{
    __shared__ float t[32][33];
    const int k0 = blockIdx.y * 32, n0 = blockIdx.x * 32;
    const int tx = threadIdx.x & 31, ty = threadIdx.x >> 5;
#pragma unroll
    for (int i = 0; i < 32; i += 8)
        t[ty + i][tx] = in[(size_t)(k0 + ty + i) * N + n0 + tx];
    __syncthreads();
#pragma unroll
    for (int i = 0; i < 32; i += 8)
        hi[(size_t)(n0 + ty + i) * K + k0 + tx] = __float2half_rn(t[tx][ty + i]);
}

// ---------------------------------------------------------------------------
// Single-term fp16 GEMM, f32 accumulate: C = A[M,K]*B[N,K]^T
// 128x64 CTA tile, 256 threads (8 warps 4m x 2n), BK=32, 2-stage cp.async,
// 3 CTAs/SM. smem/stage: Ah 128x80 + Bh 64x80 = 15360 B.
// Output: fp16 (Ch != null) or f32 + bias.
// ---------------------------------------------------------------------------
#define SROWB 80
#define OB_H  10240               // 128*80
#define STG   15360

__global__ __launch_bounds__(256, 3)
void gemm_mma(const __half* __restrict__ Ah, const __half* __restrict__ Bh,
              float* __restrict__ C, __half* __restrict__ Ch,
              int Nout, int K, const float* __restrict__ bias)
{
    extern __shared__ char sm[];
    const uint32_t sb = smem_to_u32(sm);
    const int tid = threadIdx.x;
    const int wid = tid >> 5, lane = tid & 31;
    const int wm = wid >> 1, wn = wid & 1;
    const int brow = blockIdx.y * 128, bcol = blockIdx.x * 64;
    const int nch = K / 32;

    float accF[2][4][4];
#pragma unroll
    for (int mt = 0; mt < 2; mt++)
#pragma unroll
        for (int nt = 0; nt < 4; nt++)
#pragma unroll
            for (int i = 0; i < 4; i++) accF[mt][nt][i] = 0.f;

    const int lr = tid >> 2;
    const int lc = (tid & 3);
    const uint32_t ldst = (uint32_t)lr * SROWB + lc * 16;
    const __half* pA0 = Ah + (size_t)(brow + lr) * K + lc * 8;
    const __half* pA1 = Ah + (size_t)(brow + lr + 64) * K + lc * 8;
    const __half* pB  = Bh + (size_t)(bcol + lr) * K + lc * 8;

    auto issue = [&](int c) {
        const uint32_t base = sb + (uint32_t)(c & 1) * STG + ldst;
        const int koff = c * 32;
        cpasync16(base,               pA0 + koff);
        cpasync16(base + 64 * SROWB,  pA1 + koff);
        cpasync16(base + OB_H,        pB  + koff);
    };

    issue(0); CP_COMMIT;

    const uint32_t arow  = sb + (uint32_t)(wm * 32 + (lane & 15)) * SROWB + (lane >> 4) * 16;
    const uint32_t brow_s = sb + (uint32_t)(wn * 32 + (lane & 15)) * SROWB + (lane >> 4) * 16;

    for (int c = 0; c < nch; c++) {
        if (c + 1 < nch) { issue(c + 1); CP_COMMIT; CP_WAIT1; }
        else             { CP_WAIT0; }
        __syncthreads();
        const uint32_t boff = (uint32_t)(c & 1) * STG;
#pragma unroll
        for (int ks = 0; ks < 2; ks++) {
            const uint32_t kso = boff + ks * 32;
            uint32_t af[2][4];
#pragma unroll
            for (int mt = 0; mt < 2; mt++)
                ldsm4(af[mt], arow + mt * 16 * SROWB + kso);
            uint32_t bf[4][2];
#pragma unroll
            for (int nb = 0; nb < 2; nb++) {
                uint32_t t[4];
                ldsm4(t, brow_s + OB_H + nb * 16 * SROWB + kso);
                bf[nb * 2 + 0][0] = t[0]; bf[nb * 2 + 0][1] = t[2];
                bf[nb * 2 + 1][0] = t[1]; bf[nb * 2 + 1][1] = t[3];
            }
#pragma unroll
            for (int mt = 0; mt < 2; mt++)
#pragma unroll
                for (int nt = 0; nt < 4; nt++)
                    mma16816(accF[mt][nt], af[mt], bf[nt][0], bf[nt][1]);
        }
        __syncthreads();
    }

    const int tg = lane >> 2, tq = lane & 3;
    if (Ch) {
#pragma unroll
        for (int mt = 0; mt < 2; mt++) {
            const int row = brow + wm * 32 + mt * 16 + tg;
#pragma unroll
            for (int nt = 0; nt < 4; nt++) {
                const int col = bcol + wn * 32 + nt * 8 + tq * 2;
                *(uint32_t*)&Ch[(size_t)row * Nout + col] =
                    packh2f(accF[mt][nt][0], accF[mt][nt][1]);
                *(uint32_t*)&Ch[(size_t)(row + 8) * Nout + col] =
                    packh2f(accF[mt][nt][2], accF[mt][nt][3]);
            }
        }
    } else {
#pragma unroll
        for (int mt = 0; mt < 2; mt++) {
            const int row = brow + wm * 32 + mt * 16 + tg;
#pragma unroll
            for (int nt = 0; nt < 4; nt++) {
                const int col = bcol + wn * 32 + nt * 8 + tq * 2;
                float b0 = 0.f, b1 = 0.f;
                if (bias) { b0 = bias[col]; b1 = bias[col + 1]; }
                *(float2*)&C[(size_t)row * Nout + col] =
                    make_float2(accF[mt][nt][0] + b0, accF[mt][nt][1] + b1);
                *(float2*)&C[(size_t)(row + 8) * Nout + col] =
                    make_float2(accF[mt][nt][2] + b0, accF[mt][nt][3] + b1);
            }
        }
    }
}

// ---------------------------------------------------------------------------
// Pure-fp16 flash attention (f32 softmax/accumulators), causal.
// grid (B*HEADS, SEQ/64), 128 threads, 4 CTAs/SM.
// smem: Qh (9216) + 2 stages x (Kh,Vh) (2 x 9216) = 46080 B
// ---------------------------------------------------------------------------
#define VROWB 144
#define TILEB 9216                 // 64 * 144
#define STAGEB (2 * TILEB)         // 18432

__global__ __launch_bounds__(128, 4)
void flash_mma(__half* __restrict__ oh)
{
    extern __shared__ char sm[];
    const uint32_t sb = smem_to_u32(sm);
    const uint32_t oQh = 0, oStage = TILEB;

    const int bh = blockIdx.x;
    const int b = bh / HEADS, h = bh % HEADS;
    const int qb = blockIdx.y;
    const int tid = threadIdx.x;
    const int warp = tid >> 5, lane = tid & 31;
    const int tg = lane >> 2, tq = lane & 3;

    const size_t rowbase = (size_t)(b * SEQ) * QKV3;
    const __half* Qh = g_qkvh + rowbase + h * DHEAD;
    const __half* Kh = Qh + INNER;
    const __half* Vh = Qh + 2 * INNER;

    auto issue_kv = [&](int kb2, int s) {
        const uint32_t st = sb + oStage + (uint32_t)s * STAGEB;
        const __half* srcs[2] = {
            Kh + (size_t)(kb2 * 64) * QKV3, Vh + (size_t)(kb2 * 64) * QKV3 };
#pragma unroll
        for (int i = 0; i < 2; i++)
#pragma unroll
            for (int j = 0; j < 4; j++) {
                const int idx = tid + j * 128;
                const int r = idx >> 3, ch = idx & 7;
                cpasync16(st + i * TILEB + r * VROWB + ch * 16,
                          srcs[i] + (size_t)r * QKV3 + ch * 8);
            }
    };

    issue_kv(0, 0); CP_COMMIT;

    // Q tile (plain loads, once)
    for (int idx = tid; idx < 512; idx += 128) {
        const int r = idx >> 3, ch = idx & 7;
        const size_t src = (size_t)(qb * 64 + r) * QKV3 + ch * 8;
        *(uint4*)(sm + oQh + r * VROWB + ch * 16) = *(const uint4*)(Qh + src);
    }
    __syncthreads();

    uint32_t qf[4][4];
    {
        const uint32_t qa = sb + (uint32_t)(warp * 16 + (lane & 15)) * VROWB + ((lane >> 4) << 4);
#pragma unroll
        for (int kt = 0; kt < 4; kt++)
            ldsm4(qf[kt], qa + oQh + kt * 32);
    }

    float oacc[8][4];
#pragma unroll
    for (int j = 0; j < 8; j++)
#pragma unroll
        for (int e = 0; e < 4; e++) oacc[j][e] = 0.f;
    float mrow[2] = { -1e30f, -1e30f };
    float lrow[2] = { 0.f, 0.f };

    const uint32_t fragoff = (uint32_t)(lane & 15) * VROWB + ((lane >> 4) << 4);

    for (int kb = 0; kb <= qb; kb++) {
        const int s = kb & 1;
        if (kb < qb) { issue_kv(kb + 1, s ^ 1); CP_COMMIT; CP_WAIT1; }
        else         { CP_WAIT0; }
        __syncthreads();
        const uint32_t stK = sb + oStage + (uint32_t)s * STAGEB;
        const uint32_t stV = stK + TILEB;

        // ---- S = Q K^T ----
        float sacc[8][4];
#pragma unroll
        for (int j = 0; j < 8; j++)
#pragma unroll
            for (int e = 0; e < 4; e++) sacc[j][e] = 0.f;
#pragma unroll
        for (int kt = 0; kt < 4; kt++) {
#pragma unroll
            for (int kp = 0; kp < 2; kp++) {
                uint32_t th[2][4];
#pragma unroll
                for (int u = 0; u < 2; u++) {
                    const uint32_t ka = stK + (uint32_t)((2 * kp + u) * 16) * VROWB +
                                        fragoff + kt * 32;
                    ldsm4(th[u], ka);
                }
                const int a0 = 4 * kp;
                mma16816(sacc[a0 + 0], qf[kt], th[0][0], th[0][2]);
                mma16816(sacc[a0 + 1], qf[kt], th[0][1], th[0][3]);
                mma16816(sacc[a0 + 2], qf[kt], th[1][0], th[1][2]);
                mma16816(sacc[a0 + 3], qf[kt], th[1][1], th[1][3]);
            }
        }
#pragma unroll
        for (int j = 0; j < 8; j++)
#pragma unroll
            for (int e = 0; e < 4; e++) sacc[j][e] *= SCALE;

        if (kb == qb) {
            const int r0 = warp * 16 + tg;
#pragma unroll
            for (int j = 0; j < 8; j++) {
                const int c0 = j * 8 + tq * 2;
                if (c0     > r0)     sacc[j][0] = NEGV;
                if (c0 + 1 > r0)     sacc[j][1] = NEGV;
                if (c0     > r0 + 8) sacc[j][2] = NEGV;
                if (c0 + 1 > r0 + 8) sacc[j][3] = NEGV;
            }
        }

        // ---- online softmax ----
#pragma unroll
        for (int rr = 0; rr < 2; rr++) {
            const int e0 = rr * 2;
            float mx = sacc[0][e0];
#pragma unroll
            for (int j = 0; j < 8; j++)
                mx = fmaxf(mx, fmaxf(sacc[j][e0], sacc[j][e0 + 1]));
            mx = fmaxf(mx, __shfl_xor_sync(0xffffffffu, mx, 1));
            mx = fmaxf(mx, __shfl_xor_sync(0xffffffffu, mx, 2));
            const float mn = fmaxf(mrow[rr], mx);
            const float corr = __expf(mrow[rr] - mn);
            float ps = 0.f;
#pragma unroll
            for (int j = 0; j < 8; j++) {
                const float p0 = __expf(sacc[j][e0] - mn);
                const float p1 = __expf(sacc[j][e0 + 1] - mn);
                sacc[j][e0] = p0; sacc[j][e0 + 1] = p1;
                ps += p0 + p1;
            }
            ps += __shfl_xor_sync(0xffffffffu, ps, 1);
            ps += __shfl_xor_sync(0xffffffffu, ps, 2);
            lrow[rr] = lrow[rr] * corr + ps;
            mrow[rr] = mn;
#pragma unroll
            for (int j = 0; j < 8; j++) {
                oacc[j][e0] *= corr; oacc[j][e0 + 1] *= corr;
            }
        }

        // ---- O += P V ----
#pragma unroll
        for (int kk = 0; kk < 4; kk++) {
            uint32_t aP[4];
            aP[0] = packh2f(sacc[2 * kk][0],     sacc[2 * kk][1]);
            aP[1] = packh2f(sacc[2 * kk][2],     sacc[2 * kk][3]);
            aP[2] = packh2f(sacc[2 * kk + 1][0], sacc[2 * kk + 1][1]);
            aP[3] = packh2f(sacc[2 * kk + 1][2], sacc[2 * kk + 1][3]);
#pragma unroll
            for (int dp = 0; dp < 2; dp++) {
                uint32_t vh[2][4];
#pragma unroll
                for (int u = 0; u < 2; u++) {
                    const uint32_t va = stV + (uint32_t)(kk * 16) * VROWB + fragoff +
                                        (2 * dp + u) * 32;
                    ldsm4t(vh[u], va);
                }
                const int a0 = 4 * dp;
                mma16816(oacc[a0 + 0], aP, vh[0][0], vh[0][1]);
                mma16816(oacc[a0 + 1], aP, vh[0][2], vh[0][3]);
                mma16816(oacc[a0 + 2], aP, vh[1][0], vh[1][1]);
                mma16816(oacc[a0 + 3], aP, vh[1][2], vh[1][3]);
            }
        }
        __syncthreads();
    }

    // ---- epilogue ----
    const float inv0 = 1.f / lrow[0];
    const float inv1 = 1.f / lrow[1];
    const int grow0 = b * SEQ + qb * 64 + warp * 16 + tg;
    const int grow1 = grow0 + 8;
#pragma unroll
    for (int j = 0; j < 8; j++) {
        const int col = h * DHEAD + j * 8 + tq * 2;
        *(uint32_t*)&oh[(size_t)grow0 * INNER + col] =
            packh2f(oacc[j][0] * inv0, oacc[j][1] * inv0);
        *(uint32_t*)&oh[(size_t)grow1 * INNER + col] =
            packh2f(oacc[j][2] * inv1, oacc[j][3] * inv1);
    }
}

// ---------------------------------------------------------------------------
extern "C" void kernel_launch(void* const* d_in, const int* in_sizes, int n_in,
                              void* d_out, int out_size)
{
    const float* x     = (const float*)d_in[0];
    const float* w_qkv = (const float*)d_in[1];
    const float* w_out = (const float*)d_in[2];
    const float* b_out = (const float*)d_in[3];
    float* out = (float*)d_out;

    __half *qkvh, *xh, *wqh, *woh, *ah;
    cudaGetSymbolAddress((void**)&qkvh, g_qkvh);
    cudaGetSymbolAddress((void**)&xh,   g_xh);
    cudaGetSymbolAddress((void**)&wqh,  g_wqkv_h);
    cudaGetSymbolAddress((void**)&woh,  g_wout_h);
    cudaGetSymbolAddress((void**)&ah,   g_attnh);

    cudaFuncSetAttribute(gemm_mma,  cudaFuncAttributeMaxDynamicSharedMemorySize, 2 * STG);
    cudaFuncSetAttribute(flash_mma, cudaFuncAttributeMaxDynamicSharedMemorySize,
                         TILEB + 2 * STAGEB);

    // 1) rounds
    {
        int n4 = MTOT * DIM / 4;
        round_rows<<<(n4 + 255) / 256, 256>>>(x, xh, n4);
        round_T<<<dim3(QKV3 / 32, DIM / 32), 256>>>(w_qkv, wqh, DIM, QKV3);
        round_T<<<dim3(DIM / 32, INNER / 32), 256>>>(w_out, woh, INNER, DIM);
    }
    // 2) QKV projection (fp16, f32 acc) -> fp16
    gemm_mma<<<dim3(QKV3 / 64, MTOT / 128), 256, 2 * STG>>>(
        xh, wqh, nullptr, qkvh, QKV3, DIM, nullptr);
    // 3) attention (pure fp16 inputs, f32 softmax)
    flash_mma<<<dim3(BATCH * HEADS, SEQ / 64), 128, TILEB + 2 * STAGEB>>>(ah);
    // 4) output projection + bias (f32 out)
    gemm_mma<<<dim3(DIM / 64, MTOT / 128), 256, 2 * STG>>>(
        ah, woh, out, nullptr, DIM, INNER, b_out);
}

// round 17
// speedup vs baseline: 1.5290x; 1.5290x over previous
#include <cuda_runtime.h>
#include <cuda_fp16.h>
#include <cstdint>
#include <math.h>

#define BATCH 4
#define SEQ   2048
#define DIM   1024
#define HEADS 16
#define DHEAD 64
#define INNER 1024
#define QKV3  3072
#define SCALE 0.125f
#define NEGV  (-1e9f)
#define MTOT  (BATCH * SEQ)   // 8192

// ---------------------------------------------------------------------------
// Device scratch (allocation-free)
// ---------------------------------------------------------------------------
__device__ __half  g_qkvh[(size_t)MTOT * QKV3];
__device__ __half  g_xh[(size_t)MTOT * DIM];
__device__ __half  g_wqkv_h[(size_t)QKV3 * DIM];   // [N][K]
__device__ __half  g_wout_h[(size_t)DIM * INNER];  // [N][K]
__device__ __half  g_attnh[(size_t)MTOT * INNER];

// ---------------------------------------------------------------------------
__device__ __forceinline__ uint32_t smem_to_u32(const void* p) {
    uint32_t a;
    asm("{ .reg .u64 t; cvta.to.shared.u64 t, %1; cvt.u32.u64 %0, t; }" : "=r"(a) : "l"(p));
    return a;
}
__device__ __forceinline__ void ldsm4(uint32_t (&r)[4], uint32_t addr) {
    asm volatile("ldmatrix.sync.aligned.m8n8.x4.shared.b16 {%0,%1,%2,%3}, [%4];"
        : "=r"(r[0]), "=r"(r[1]), "=r"(r[2]), "=r"(r[3]) : "r"(addr));
}
__device__ __forceinline__ void ldsm4t(uint32_t (&r)[4], uint32_t addr) {
    asm volatile("ldmatrix.sync.aligned.m8n8.x4.trans.shared.b16 {%0,%1,%2,%3}, [%4];"
        : "=r"(r[0]), "=r"(r[1]), "=r"(r[2]), "=r"(r[3]) : "r"(addr));
}
__device__ __forceinline__ void mma16816(float (&d)[4], const uint32_t (&a)[4],
                                         uint32_t b0, uint32_t b1) {
    asm volatile("mma.sync.aligned.m16n8k16.row.col.f32.f16.f16.f32 "
        "{%0,%1,%2,%3}, {%4,%5,%6,%7}, {%8,%9}, {%0,%1,%2,%3};"
        : "+f"(d[0]), "+f"(d[1]), "+f"(d[2]), "+f"(d[3])
        : "r"(a[0]), "r"(a[1]), "r"(a[2]), "r"(a[3]), "r"(b0), "r"(b1));
}
__device__ __forceinline__ void cpasync16(uint32_t dst, const void* src) {
    asm volatile("cp.async.cg.shared.global [%0], [%1], 16;" :: "r"(dst), "l"(src));
}
#define CP_COMMIT  asm volatile("cp.async.commit_group;" ::: "memory")
#define CP_WAIT1   asm volatile("cp.async.wait_group 1;" ::: "memory")
#define CP_WAIT0   asm volatile("cp.async.wait_group 0;" ::: "memory")

__device__ __forceinline__ uint32_t packh(__half a, __half b) {
    return (uint32_t)__half_as_ushort(a) | ((uint32_t)__half_as_ushort(b) << 16);
}
__device__ __forceinline__ uint32_t packh2f(float a, float b) {
    return packh(__float2half_rn(a), __float2half_rn(b));
}

// ---------------------------------------------------------------------------
// Conversion kernels
// ---------------------------------------------------------------------------
__global__ __launch_bounds__(256)
void round_rows(const float* __restrict__ in, __half* __restrict__ hi, int n4)
{
    int i = blockIdx.x * 256 + threadIdx.x;
    if (i >= n4) return;
    float4 v = ((const float4*)in)[i];
    uint2 hv;
    hv.x = packh2f(v.x, v.y);
    hv.y = packh2f(v.z, v.w);
    ((uint2*)hi)[i] = hv;
}

// in[K][N] -> out[N][K], single-fp16 round
__global__ __launch_bounds__(256)
void round_T(const float* __restrict__ in, __half* __restrict__ hi, int K, int N)
{
    __shared__ float t[32][33];
    const int k0 = blockIdx.y * 32, n0 = blockIdx.x * 32;
    const int tx = threadIdx.x & 31, ty = threadIdx.x >> 5;
#pragma unroll
    for (int i = 0; i < 32; i += 8)
        t[ty + i][tx] = in[(size_t)(k0 + ty + i) * N + n0 + tx];
    __syncthreads();
#pragma unroll
    for (int i = 0; i < 32; i += 8)
        hi[(size_t)(n0 + ty + i) * K + k0 + tx] = __float2half_rn(t[tx][ty + i]);
}

// ---------------------------------------------------------------------------
// Single-term fp16 GEMM, f32 accumulate: C = A[M,K]*B[N,K]^T
// 128x64 CTA tile, 256 threads (8 warps 4m x 2n), BK=32, 2-stage cp.async,
// 3 CTAs/SM. smem/stage: Ah 128x80 + Bh 64x80 = 15360 B.
// Output: fp16 (Ch != null) or f32 + bias.
// ---------------------------------------------------------------------------
#define SROWB 80
#define OB_H  10240               // 128*80
#define STG   15360

__global__ __launch_bounds__(256, 3)
void gemm_mma(const __half* __restrict__ Ah, const __half* __restrict__ Bh,
              float* __restrict__ C, __half* __restrict__ Ch,
              int Nout, int K, const float* __restrict__ bias)
{
    extern __shared__ char sm[];
    const uint32_t sb = smem_to_u32(sm);
    const int tid = threadIdx.x;
    const int wid = tid >> 5, lane = tid & 31;
    const int wm = wid >> 1, wn = wid & 1;
    const int brow = blockIdx.y * 128, bcol = blockIdx.x * 64;
    const int nch = K / 32;

    float accF[2][4][4];
#pragma unroll
    for (int mt = 0; mt < 2; mt++)
#pragma unroll
        for (int nt = 0; nt < 4; nt++)
#pragma unroll
            for (int i = 0; i < 4; i++) accF[mt][nt][i] = 0.f;

    const int lr = tid >> 2;
    const int lc = (tid & 3);
    const uint32_t ldst = (uint32_t)lr * SROWB + lc * 16;
    const __half* pA0 = Ah + (size_t)(brow + lr) * K + lc * 8;
    const __half* pA1 = Ah + (size_t)(brow + lr + 64) * K + lc * 8;
    const __half* pB  = Bh + (size_t)(bcol + lr) * K + lc * 8;

    auto issue = [&](int c) {
        const uint32_t base = sb + (uint32_t)(c & 1) * STG + ldst;
        const int koff = c * 32;
        cpasync16(base,               pA0 + koff);
        cpasync16(base + 64 * SROWB,  pA1 + koff);
        cpasync16(base + OB_H,        pB  + koff);
    };

    issue(0); CP_COMMIT;

    const uint32_t arow  = sb + (uint32_t)(wm * 32 + (lane & 15)) * SROWB + (lane >> 4) * 16;
    const uint32_t brow_s = sb + (uint32_t)(wn * 32 + (lane & 15)) * SROWB + (lane >> 4) * 16;

    for (int c = 0; c < nch; c++) {
        if (c + 1 < nch) { issue(c + 1); CP_COMMIT; CP_WAIT1; }
        else             { CP_WAIT0; }
        __syncthreads();
        const uint32_t boff = (uint32_t)(c & 1) * STG;
#pragma unroll
        for (int ks = 0; ks < 2; ks++) {
            const uint32_t kso = boff + ks * 32;
            uint32_t af[2][4];
#pragma unroll
            for (int mt = 0; mt < 2; mt++)
                ldsm4(af[mt], arow + mt * 16 * SROWB + kso);
            uint32_t bf[4][2];
#pragma unroll
            for (int nb = 0; nb < 2; nb++) {
                uint32_t t[4];
                ldsm4(t, brow_s + OB_H + nb * 16 * SROWB + kso);
                bf[nb * 2 + 0][0] = t[0]; bf[nb * 2 + 0][1] = t[2];
                bf[nb * 2 + 1][0] = t[1]; bf[nb * 2 + 1][1] = t[3];
            }
#pragma unroll
            for (int mt = 0; mt < 2; mt++)
#pragma unroll
                for (int nt = 0; nt < 4; nt++)
                    mma16816(accF[mt][nt], af[mt], bf[nt][0], bf[nt][1]);
        }
        __syncthreads();
    }

    const int tg = lane >> 2, tq = lane & 3;
    if (Ch) {
#pragma unroll
        for (int mt = 0; mt < 2; mt++) {
            const int row = brow + wm * 32 + mt * 16 + tg;
#pragma unroll
            for (int nt = 0; nt < 4; nt++) {
                const int col = bcol + wn * 32 + nt * 8 + tq * 2;
                *(uint32_t*)&Ch[(size_t)row * Nout + col] =
                    packh2f(accF[mt][nt][0], accF[mt][nt][1]);
                *(uint32_t*)&Ch[(size_t)(row + 8) * Nout + col] =
                    packh2f(accF[mt][nt][2], accF[mt][nt][3]);
            }
        }
    } else {
#pragma unroll
        for (int mt = 0; mt < 2; mt++) {
            const int row = brow + wm * 32 + mt * 16 + tg;
#pragma unroll
            for (int nt = 0; nt < 4; nt++) {
                const int col = bcol + wn * 32 + nt * 8 + tq * 2;
                float b0 = 0.f, b1 = 0.f;
                if (bias) { b0 = bias[col]; b1 = bias[col + 1]; }
                *(float2*)&C[(size_t)row * Nout + col] =
                    make_float2(accF[mt][nt][0] + b0, accF[mt][nt][1] + b1);
                *(float2*)&C[(size_t)(row + 8) * Nout + col] =
                    make_float2(accF[mt][nt][2] + b0, accF[mt][nt][3] + b1);
            }
        }
    }
}

// ---------------------------------------------------------------------------
// Pure-fp16 flash attention (f32 softmax/accumulators), causal.
// grid (B*HEADS, SEQ/64), 128 threads, 4 CTAs/SM.
// smem: Qh (9216) + 2 stages x (Kh,Vh) (2 x 9216) = 46080 B
// ---------------------------------------------------------------------------
#define VROWB 144
#define TILEB 9216                 // 64 * 144
#define STAGEB (2 * TILEB)         // 18432

__global__ __launch_bounds__(128, 4)
void flash_mma(__half* __restrict__ oh)
{
    extern __shared__ char sm[];
    const uint32_t sb = smem_to_u32(sm);
    const uint32_t oQh = 0, oStage = TILEB;

    const int bh = blockIdx.x;
    const int b = bh / HEADS, h = bh % HEADS;
    const int qb = blockIdx.y;
    const int tid = threadIdx.x;
    const int warp = tid >> 5, lane = tid & 31;
    const int tg = lane >> 2, tq = lane & 3;

    const size_t rowbase = (size_t)(b * SEQ) * QKV3;
    const __half* Qh = g_qkvh + rowbase + h * DHEAD;
    const __half* Kh = Qh + INNER;
    const __half* Vh = Qh + 2 * INNER;

    auto issue_kv = [&](int kb2, int s) {
        const uint32_t st = sb + oStage + (uint32_t)s * STAGEB;
        const __half* srcs[2] = {
            Kh + (size_t)(kb2 * 64) * QKV3, Vh + (size_t)(kb2 * 64) * QKV3 };
#pragma unroll
        for (int i = 0; i < 2; i++)
#pragma unroll
            for (int j = 0; j < 4; j++) {
                const int idx = tid + j * 128;
                const int r = idx >> 3, ch = idx & 7;
                cpasync16(st + i * TILEB + r * VROWB + ch * 16,
                          srcs[i] + (size_t)r * QKV3 + ch * 8);
            }
    };

    issue_kv(0, 0); CP_COMMIT;

    // Q tile (plain loads, once)
    for (int idx = tid; idx < 512; idx += 128) {
        const int r = idx >> 3, ch = idx & 7;
        const size_t src = (size_t)(qb * 64 + r) * QKV3 + ch * 8;
        *(uint4*)(sm + oQh + r * VROWB + ch * 16) = *(const uint4*)(Qh + src);
    }
    __syncthreads();

    uint32_t qf[4][4];
    {
        const uint32_t qa = sb + (uint32_t)(warp * 16 + (lane & 15)) * VROWB + ((lane >> 4) << 4);
#pragma unroll
        for (int kt = 0; kt < 4; kt++)
            ldsm4(qf[kt], qa + oQh + kt * 32);
    }

    float oacc[8][4];
#pragma unroll
    for (int j = 0; j < 8; j++)
#pragma unroll
        for (int e = 0; e < 4; e++) oacc[j][e] = 0.f;
    float mrow[2] = { -1e30f, -1e30f };
    float lrow[2] = { 0.f, 0.f };

    const uint32_t fragoff = (uint32_t)(lane & 15) * VROWB + ((lane >> 4) << 4);

    for (int kb = 0; kb <= qb; kb++) {
        const int s = kb & 1;
        if (kb < qb) { issue_kv(kb + 1, s ^ 1); CP_COMMIT; CP_WAIT1; }
        else         { CP_WAIT0; }
        __syncthreads();
        const uint32_t stK = sb + oStage + (uint32_t)s * STAGEB;
        const uint32_t stV = stK + TILEB;

        // ---- S = Q K^T ----
        float sacc[8][4];
#pragma unroll
        for (int j = 0; j < 8; j++)
#pragma unroll
            for (int e = 0; e < 4; e++) sacc[j][e] = 0.f;
#pragma unroll
        for (int kt = 0; kt < 4; kt++) {
#pragma unroll
            for (int kp = 0; kp < 2; kp++) {
                uint32_t th[2][4];
#pragma unroll
                for (int u = 0; u < 2; u++) {
                    const uint32_t ka = stK + (uint32_t)((2 * kp + u) * 16) * VROWB +
                                        fragoff + kt * 32;
                    ldsm4(th[u], ka);
                }
                const int a0 = 4 * kp;
                mma16816(sacc[a0 + 0], qf[kt], th[0][0], th[0][2]);
                mma16816(sacc[a0 + 1], qf[kt], th[0][1], th[0][3]);
                mma16816(sacc[a0 + 2], qf[kt], th[1][0], th[1][2]);
                mma16816(sacc[a0 + 3], qf[kt], th[1][1], th[1][3]);
            }
        }
#pragma unroll
        for (int j = 0; j < 8; j++)
#pragma unroll
            for (int e = 0; e < 4; e++) sacc[j][e] *= SCALE;

        if (kb == qb) {
            const int r0 = warp * 16 + tg;
#pragma unroll
            for (int j = 0; j < 8; j++) {
                const int c0 = j * 8 + tq * 2;
                if (c0     > r0)     sacc[j][0] = NEGV;
                if (c0 + 1 > r0)     sacc[j][1] = NEGV;
                if (c0     > r0 + 8) sacc[j][2] = NEGV;
                if (c0 + 1 > r0 + 8) sacc[j][3] = NEGV;
            }
        }

        // ---- online softmax ----
#pragma unroll
        for (int rr = 0; rr < 2; rr++) {
            const int e0 = rr * 2;
            float mx = sacc[0][e0];
#pragma unroll
            for (int j = 0; j < 8; j++)
                mx = fmaxf(mx, fmaxf(sacc[j][e0], sacc[j][e0 + 1]));
            mx = fmaxf(mx, __shfl_xor_sync(0xffffffffu, mx, 1));
            mx = fmaxf(mx, __shfl_xor_sync(0xffffffffu, mx, 2));
            const float mn = fmaxf(mrow[rr], mx);
            const float corr = __expf(mrow[rr] - mn);
            float ps = 0.f;
#pragma unroll
            for (int j = 0; j < 8; j++) {
                const float p0 = __expf(sacc[j][e0] - mn);
                const float p1 = __expf(sacc[j][e0 + 1] - mn);
                sacc[j][e0] = p0; sacc[j][e0 + 1] = p1;
                ps += p0 + p1;
            }
            ps += __shfl_xor_sync(0xffffffffu, ps, 1);
            ps += __shfl_xor_sync(0xffffffffu, ps, 2);
            lrow[rr] = lrow[rr] * corr + ps;
            mrow[rr] = mn;
#pragma unroll
            for (int j = 0; j < 8; j++) {
                oacc[j][e0] *= corr; oacc[j][e0 + 1] *= corr;
            }
        }

        // ---- O += P V ----
#pragma unroll
        for (int kk = 0; kk < 4; kk++) {
            uint32_t aP[4];
            aP[0] = packh2f(sacc[2 * kk][0],     sacc[2 * kk][1]);
            aP[1] = packh2f(sacc[2 * kk][2],     sacc[2 * kk][3]);
            aP[2] = packh2f(sacc[2 * kk + 1][0], sacc[2 * kk + 1][1]);
            aP[3] = packh2f(sacc[2 * kk + 1][2], sacc[2 * kk + 1][3]);
#pragma unroll
            for (int dp = 0; dp < 2; dp++) {
                uint32_t vh[2][4];
#pragma unroll
                for (int u = 0; u < 2; u++) {
                    const uint32_t va = stV + (uint32_t)(kk * 16) * VROWB + fragoff +
                                        (2 * dp + u) * 32;
                    ldsm4t(vh[u], va);
                }
                const int a0 = 4 * dp;
                mma16816(oacc[a0 + 0], aP, vh[0][0], vh[0][1]);
                mma16816(oacc[a0 + 1], aP, vh[0][2], vh[0][3]);
                mma16816(oacc[a0 + 2], aP, vh[1][0], vh[1][1]);
                mma16816(oacc[a0 + 3], aP, vh[1][2], vh[1][3]);
            }
        }
        __syncthreads();
    }

    // ---- epilogue ----
    const float inv0 = 1.f / lrow[0];
    const float inv1 = 1.f / lrow[1];
    const int grow0 = b * SEQ + qb * 64 + warp * 16 + tg;
    const int grow1 = grow0 + 8;
#pragma unroll
    for (int j = 0; j < 8; j++) {
        const int col = h * DHEAD + j * 8 + tq * 2;
        *(uint32_t*)&oh[(size_t)grow0 * INNER + col] =
            packh2f(oacc[j][0] * inv0, oacc[j][1] * inv0);
        *(uint32_t*)&oh[(size_t)grow1 * INNER + col] =
            packh2f(oacc[j][2] * inv1, oacc[j][3] * inv1);
    }
}

// ---------------------------------------------------------------------------
extern "C" void kernel_launch(void* const* d_in, const int* in_sizes, int n_in,
                              void* d_out, int out_size)
{
    const float* x     = (const float*)d_in[0];
    const float* w_qkv = (const float*)d_in[1];
    const float* w_out = (const float*)d_in[2];
    const float* b_out = (const float*)d_in[3];
    float* out = (float*)d_out;

    __half *qkvh, *xh, *wqh, *woh, *ah;
    cudaGetSymbolAddress((void**)&qkvh, g_qkvh);
    cudaGetSymbolAddress((void**)&xh,   g_xh);
    cudaGetSymbolAddress((void**)&wqh,  g_wqkv_h);
    cudaGetSymbolAddress((void**)&woh,  g_wout_h);
    cudaGetSymbolAddress((void**)&ah,   g_attnh);

    cudaFuncSetAttribute(gemm_mma,  cudaFuncAttributeMaxDynamicSharedMemorySize, 2 * STG);
    cudaFuncSetAttribute(flash_mma, cudaFuncAttributeMaxDynamicSharedMemorySize,
                         TILEB + 2 * STAGEB);

    // 1) rounds
    {
        int n4 = MTOT * DIM / 4;
        round_rows<<<(n4 + 255) / 256, 256>>>(x, xh, n4);
        round_T<<<dim3(QKV3 / 32, DIM / 32), 256>>>(w_qkv, wqh, DIM, QKV3);
        round_T<<<dim3(DIM / 32, INNER / 32), 256>>>(w_out, woh, INNER, DIM);
    }
    // 2) QKV projection (fp16, f32 acc) -> fp16
    gemm_mma<<<dim3(QKV3 / 64, MTOT / 128), 256, 2 * STG>>>(
        xh, wqh, nullptr, qkvh, QKV3, DIM, nullptr);
    // 3) attention (pure fp16 inputs, f32 softmax)
    flash_mma<<<dim3(BATCH * HEADS, SEQ / 64), 128, TILEB + 2 * STAGEB>>>(ah);
    // 4) output projection + bias (f32 out)
    gemm_mma<<<dim3(DIM / 64, MTOT / 128), 256, 2 * STG>>>(
        ah, woh, out, nullptr, DIM, INNER, b_out);
}